// round 1
// baseline (speedup 1.0000x reference)
#include <cuda_runtime.h>
#include <cuda_bf16.h>
#include <math.h>

// ---------------------------------------------------------------------------
// Problem constants
// ---------------------------------------------------------------------------
#define BN   2
#define CH   128
#define HH   128
#define WW   128
#define TOT  (BN*CH*HH*WW)          // 4194304
#define NSEQ (BN*CH*HH)             // 32768 sequences of length 128 floats
#define D_INNER 32
#define D_STATE 16
#define GCN  16
#define LSEQ 8
#define GROUPS 4
#define GRP_CNT ((CH/GROUPS)*HH*WW) // 524288 elements per (b, group)

// ---------------------------------------------------------------------------
// Scratch (static device memory; no allocation allowed)
// ---------------------------------------------------------------------------
__device__ float g_y[TOT];       // conv2d output
__device__ float g_m[TOT];       // mamba output (pre-GroupNorm)
__device__ float g_stats[16];    // (b,group) -> {sum, sumsq}

// ---------------------------------------------------------------------------
// Kernel 0: zero the stats accumulators
// ---------------------------------------------------------------------------
__global__ void zero_stats_kernel() {
    if (threadIdx.x < 16) g_stats[threadIdx.x] = 0.f;
}

// ---------------------------------------------------------------------------
// Kernel 1: 3x3 conv, 128->128 channels, pad 1, + bias.
// Grid: (4 co-groups, 128 h, 2 b). Block: 256 threads.
// Thread t: co = t>>3 (within group of 32), w-segment = (t&7)*16.
// ---------------------------------------------------------------------------
#define CI_T 16
__global__ __launch_bounds__(256) void conv3x3_kernel(
    const float* __restrict__ x, const float* __restrict__ w,
    const float* __restrict__ bias)
{
    __shared__ __align__(16) float xs[CI_T][3][132];   // padded row: col = w+1
    __shared__ float ws[32][CI_T][9];

    const int cog = blockIdx.x;   // 0..3
    const int h   = blockIdx.y;   // 0..127
    const int b   = blockIdx.z;   // 0..1
    const int tid = threadIdx.x;
    const int co    = tid >> 3;       // 0..31
    const int wbase = (tid & 7) << 4; // 0,16,...,112

    float acc[16];
#pragma unroll
    for (int j = 0; j < 16; j++) acc[j] = 0.f;

    for (int ci0 = 0; ci0 < CH; ci0 += CI_T) {
        // load input patch: CI_T channels x 3 rows x 130 cols (zero-padded)
        for (int idx = tid; idx < CI_T * 3 * 130; idx += 256) {
            int ci  = idx / 390;
            int rem = idx - ci * 390;
            int r   = rem / 130;
            int col = rem - r * 130;
            int hh  = h - 1 + r;
            int ww  = col - 1;
            float v = 0.f;
            if (hh >= 0 && hh < HH && ww >= 0 && ww < WW)
                v = x[(((size_t)b * CH + (ci0 + ci)) * HH + hh) * WW + ww];
            xs[ci][r][col] = v;
        }
        // load weights: 32 co x CI_T ci x 9
        for (int idx = tid; idx < 32 * CI_T * 9; idx += 256) {
            int coi = idx / (CI_T * 9);
            int rem = idx - coi * (CI_T * 9);
            int ci  = rem / 9;
            int k   = rem - ci * 9;
            ws[coi][ci][k] = w[(((size_t)(cog * 32 + coi)) * CH + (ci0 + ci)) * 9 + k];
        }
        __syncthreads();

        for (int ci = 0; ci < CI_T; ci++) {
            float wr[9];
#pragma unroll
            for (int k = 0; k < 9; k++) wr[k] = ws[co][ci][k];
#pragma unroll
            for (int r = 0; r < 3; r++) {
                float rr[18];
                const float4* p4 = (const float4*)&xs[ci][r][wbase];
                float4 q;
                q = p4[0]; rr[0]=q.x; rr[1]=q.y; rr[2]=q.z; rr[3]=q.w;
                q = p4[1]; rr[4]=q.x; rr[5]=q.y; rr[6]=q.z; rr[7]=q.w;
                q = p4[2]; rr[8]=q.x; rr[9]=q.y; rr[10]=q.z; rr[11]=q.w;
                q = p4[3]; rr[12]=q.x; rr[13]=q.y; rr[14]=q.z; rr[15]=q.w;
                float2 t2 = *(const float2*)&xs[ci][r][wbase + 16];
                rr[16]=t2.x; rr[17]=t2.y;
#pragma unroll
                for (int kw = 0; kw < 3; kw++) {
                    float wt = wr[r * 3 + kw];
#pragma unroll
                    for (int j = 0; j < 16; j++)
                        acc[j] = fmaf(wt, rr[j + kw], acc[j]);
                }
            }
        }
        __syncthreads();
    }

    const int co_abs = cog * 32 + co;
    const float bv = bias[co_abs];
    float* yp = &g_y[(((size_t)b * CH + co_abs) * HH + h) * WW + wbase];
#pragma unroll
    for (int j = 0; j < 16; j += 4) {
        float4 o;
        o.x = acc[j]   + bv; o.y = acc[j+1] + bv;
        o.z = acc[j+2] + bv; o.w = acc[j+3] + bv;
        *(float4*)&yp[j] = o;
    }
}

// ---------------------------------------------------------------------------
// Kernel 2: Mamba over 32768 sequences, one warp per sequence (lane = d_inner).
// Also accumulates GroupNorm sum/sumsq (group is constant per block).
// Grid: 4096 blocks x 256 threads (8 warps).
// ---------------------------------------------------------------------------
__global__ __launch_bounds__(256) void mamba_kernel(
    const float* __restrict__ in_proj_w,   // (64,16)
    const float* __restrict__ c1w,         // (32,1,4)
    const float* __restrict__ c1b,         // (32)
    const float* __restrict__ xpw,         // (33,32)
    const float* __restrict__ dtw,         // (32,1)
    const float* __restrict__ dtb,         // (32)
    const float* __restrict__ A_log,       // (32,16)
    const float* __restrict__ Dp,          // (32)
    const float* __restrict__ opw)         // (16,32)
{
    // block-wide weights (transposed for conflict-free lane reads)
    __shared__ float s_ipw[16 * 64];    // [k][e]
    __shared__ float s_xpwt[32 * 33];   // [d][e]
    __shared__ float s_At[16 * 32];     // [s][d] : A = -exp(A_log)
    __shared__ float s_opwt[32 * 16];   // [d][g]
    __shared__ float s_c1w[32 * 4];
    __shared__ float s_c1b[32], s_dtw[32], s_dtb[32], s_D[32];
    // per-warp buffers
    __shared__ float s_seq[8][128];
    __shared__ float s_xc[8][LSEQ * 32];   // xc, later reused for ym
    __shared__ float s_bc[8][LSEQ * 32];   // [l*32 + s] = B, [l*32+16+s] = C
    __shared__ float sm_s1, sm_s2;

    const int tid = threadIdx.x;

    for (int idx = tid; idx < 16 * 64; idx += 256) {
        int k = idx >> 6, e = idx & 63;
        s_ipw[idx] = in_proj_w[e * 16 + k];
    }
    for (int idx = tid; idx < 32 * 33; idx += 256) {
        int d = idx / 33, e = idx - d * 33;
        s_xpwt[idx] = xpw[e * 32 + d];
    }
    for (int idx = tid; idx < 16 * 32; idx += 256) {
        int s = idx >> 5, d = idx & 31;
        s_At[idx] = -__expf(A_log[d * 16 + s]);
    }
    for (int idx = tid; idx < 32 * 16; idx += 256) {
        int d = idx >> 4, g = idx & 15;
        s_opwt[idx] = opw[g * 32 + d];
    }
    if (tid < 128) s_c1w[tid] = c1w[tid];
    if (tid < 32) {
        s_c1b[tid] = c1b[tid];
        s_dtw[tid] = dtw[tid];
        s_dtb[tid] = dtb[tid];
        s_D[tid]   = Dp[tid];
    }
    if (tid == 0) { sm_s1 = 0.f; sm_s2 = 0.f; }
    __syncthreads();

    const int warp = tid >> 5;
    const int lane = tid & 31;
    const int n = blockIdx.x * 8 + warp;     // sequence id, < 32768
    const int c = (n >> 7) & 127;            // channel (same group for whole block)
    const int b = n >> 14;

    const float* yrow = g_y + (size_t)n * 128;
    float* seq = s_seq[warp];
#pragma unroll
    for (int i = 0; i < 4; i++) seq[i * 32 + lane] = yrow[i * 32 + lane];
    __syncwarp();

    // in_proj: xi (e=lane), z (e=32+lane)
    float xi[LSEQ], zv[LSEQ];
#pragma unroll
    for (int l = 0; l < LSEQ; l++) {
        float sx = 0.f, sz = 0.f;
#pragma unroll
        for (int k = 0; k < GCN; k++) {
            float sv = seq[l * GCN + k];
            sx = fmaf(sv, s_ipw[k * 64 + lane], sx);
            sz = fmaf(sv, s_ipw[k * 64 + 32 + lane], sz);
        }
        xi[l] = sx; zv[l] = sz;
    }

    // causal depthwise conv1d (kernel 4) + SiLU
    float cw0 = s_c1w[lane * 4 + 0], cw1 = s_c1w[lane * 4 + 1];
    float cw2 = s_c1w[lane * 4 + 2], cw3 = s_c1w[lane * 4 + 3];
    float cb = s_c1b[lane];
    float xc[LSEQ];
#pragma unroll
    for (int l = 0; l < LSEQ; l++) {
        float a = fmaf(cw3, xi[l], cb);
        if (l >= 1) a = fmaf(cw2, xi[l - 1], a);
        if (l >= 2) a = fmaf(cw1, xi[l - 2], a);
        if (l >= 3) a = fmaf(cw0, xi[l - 3], a);
        a = a * (1.f / (1.f + __expf(-a)));      // silu
        xc[l] = a;
        s_xc[warp][l * 32 + lane] = a;
    }
    __syncwarp();

    // x_proj: dt_in (redundant across lanes) and B/C (lane -> e = 1+lane)
    float dtin[LSEQ];
#pragma unroll
    for (int l = 0; l < LSEQ; l++) {
        float s0 = 0.f, s1 = 0.f;
#pragma unroll
        for (int d = 0; d < D_INNER; d++) {
            float xv = s_xc[warp][l * 32 + d];
            s0 = fmaf(xv, s_xpwt[d * 33], s0);
            s1 = fmaf(xv, s_xpwt[d * 33 + 1 + lane], s1);
        }
        dtin[l] = s0;
        s_bc[warp][l * 32 + lane] = s1;   // lanes 0..15 = B[s], 16..31 = C[s]
    }
    __syncwarp();

    // selective scan (lane = d_inner channel; state in registers)
    float Areg[D_STATE];
#pragma unroll
    for (int s = 0; s < D_STATE; s++) Areg[s] = s_At[s * 32 + lane];
    float hreg[D_STATE];
#pragma unroll
    for (int s = 0; s < D_STATE; s++) hreg[s] = 0.f;

    const float dtwv = s_dtw[lane], dtbv = s_dtb[lane], Dv = s_D[lane];

#pragma unroll
    for (int l = 0; l < LSEQ; l++) {
        float pre = fmaf(dtin[l], dtwv, dtbv);
        float dt = (pre > 20.f) ? pre : log1pf(__expf(pre));  // softplus
        float cBx = dt * xc[l];
        float yacc = 0.f;
#pragma unroll
        for (int s = 0; s < D_STATE; s++) {
            float dA = __expf(dt * Areg[s]);
            float Bv = s_bc[warp][l * 32 + s];
            float Cv = s_bc[warp][l * 32 + 16 + s];
            hreg[s] = fmaf(dA, hreg[s], cBx * Bv);
            yacc = fmaf(hreg[s], Cv, yacc);
        }
        float ym = fmaf(Dv, xc[l], yacc);
        float zz = zv[l];
        ym = ym * (zz * (1.f / (1.f + __expf(-zz))));   // * silu(z)
        s_xc[warp][l * 32 + lane] = ym;                 // reuse buffer for ym
    }
    __syncwarp();

    // out_proj: 8 l x 16 g outputs; lane -> g = lane&15, half = lane>>4
    float ps1 = 0.f, ps2 = 0.f;
    const int g = lane & 15;
    const int lh = lane >> 4;
    float* outp = g_m + (size_t)n * 128;
#pragma unroll
    for (int i = 0; i < 4; i++) {
        int l = i * 2 + lh;
        float acc = 0.f;
#pragma unroll
        for (int d = 0; d < D_INNER; d++)
            acc = fmaf(s_xc[warp][l * 32 + d], s_opwt[d * 16 + g], acc);
        outp[l * GCN + g] = acc;
        ps1 += acc;
        ps2 = fmaf(acc, acc, ps2);
    }

    // warp reduce -> shared -> one global atomic pair per block
#pragma unroll
    for (int off = 16; off; off >>= 1) {
        ps1 += __shfl_xor_sync(0xFFFFFFFFu, ps1, off);
        ps2 += __shfl_xor_sync(0xFFFFFFFFu, ps2, off);
    }
    if (lane == 0) {
        atomicAdd(&sm_s1, ps1);
        atomicAdd(&sm_s2, ps2);
    }
    __syncthreads();
    if (tid == 0) {
        int bg = b * 4 + (c >> 5);
        atomicAdd(&g_stats[bg * 2 + 0], sm_s1);
        atomicAdd(&g_stats[bg * 2 + 1], sm_s2);
    }
}

// ---------------------------------------------------------------------------
// Kernel 3: GroupNorm + SiLU + residual add. float4 grid-stride.
// ---------------------------------------------------------------------------
__global__ __launch_bounds__(256) void apply_kernel(
    const float* __restrict__ x, const float* __restrict__ gnw,
    const float* __restrict__ gnb, float* __restrict__ out)
{
    int idx4 = blockIdx.x * blockDim.x + threadIdx.x;
    if (idx4 >= TOT / 4) return;
    int idx = idx4 * 4;
    int c  = (idx >> 14) & 127;
    int bg = (idx >> 21) * 4 + (c >> 5);
    float s1 = g_stats[bg * 2], s2 = g_stats[bg * 2 + 1];
    const float inv_cnt = 1.f / (float)GRP_CNT;
    float mu  = s1 * inv_cnt;
    float var = fmaf(s2, inv_cnt, -mu * mu);
    float rstd = rsqrtf(var + 1e-5f);
    float gw = gnw[c] * rstd;
    float gb = gnb[c];

    float4 xv = *(const float4*)&x[idx];
    float4 mv = *(const float4*)&g_m[idx];
    float4 o;
    {
        float t = fmaf(mv.x - mu, gw, gb);
        o.x = xv.x + t * (1.f / (1.f + __expf(-t)));
    }
    {
        float t = fmaf(mv.y - mu, gw, gb);
        o.y = xv.y + t * (1.f / (1.f + __expf(-t)));
    }
    {
        float t = fmaf(mv.z - mu, gw, gb);
        o.z = xv.z + t * (1.f / (1.f + __expf(-t)));
    }
    {
        float t = fmaf(mv.w - mu, gw, gb);
        o.w = xv.w + t * (1.f / (1.f + __expf(-t)));
    }
    *(float4*)&out[idx] = o;
}

// ---------------------------------------------------------------------------
// Launch
// ---------------------------------------------------------------------------
extern "C" void kernel_launch(void* const* d_in, const int* in_sizes, int n_in,
                              void* d_out, int out_size)
{
    const float* x          = (const float*)d_in[0];
    const float* conv_w     = (const float*)d_in[1];
    const float* conv_b     = (const float*)d_in[2];
    const float* gn_w       = (const float*)d_in[3];
    const float* gn_b       = (const float*)d_in[4];
    const float* in_proj_w  = (const float*)d_in[5];
    const float* conv1d_w   = (const float*)d_in[6];
    const float* conv1d_b   = (const float*)d_in[7];
    const float* x_proj_w   = (const float*)d_in[8];
    const float* dt_proj_w  = (const float*)d_in[9];
    const float* dt_proj_b  = (const float*)d_in[10];
    const float* A_log      = (const float*)d_in[11];
    const float* Dp         = (const float*)d_in[12];
    const float* out_proj_w = (const float*)d_in[13];
    float* out = (float*)d_out;

    zero_stats_kernel<<<1, 32>>>();

    dim3 cgrid(4, HH, BN);
    conv3x3_kernel<<<cgrid, 256>>>(x, conv_w, conv_b);

    mamba_kernel<<<NSEQ / 8, 256>>>(in_proj_w, conv1d_w, conv1d_b, x_proj_w,
                                    dt_proj_w, dt_proj_b, A_log, Dp, out_proj_w);

    apply_kernel<<<(TOT / 4 + 255) / 256, 256>>>(x, gn_w, gn_b, out);
}

// round 3
// speedup vs baseline: 3.5364x; 3.5364x over previous
#include <cuda_runtime.h>
#include <cuda_bf16.h>
#include <math.h>

// ---------------------------------------------------------------------------
// Problem constants
// ---------------------------------------------------------------------------
#define BN   2
#define CH   128
#define HH   128
#define WW   128
#define TOT  (BN*CH*HH*WW)          // 4194304
#define NSEQ (BN*CH*HH)             // 32768 sequences
#define D_INNER 32
#define D_STATE 16
#define GCN  16
#define LSEQ 8
#define GROUPS 4
#define GRP_CNT ((CH/GROUPS)*HH*WW) // 524288 elements per (b, group)

typedef unsigned long long u64;

// packed fp32x2 FMA (Blackwell): 2 FMAs per instruction, exact fma.rn per half
#define FMA2(d,a,b,c) asm("fma.rn.f32x2 %0, %1, %2, %3;" : "=l"(d) : "l"(a), "l"(b), "l"(c))
#define PK2(d,lo,hi)  asm("mov.b64 %0, {%1, %2};" : "=l"(d) : "r"(__float_as_uint(lo)), "r"(__float_as_uint(hi)))
#define UPK2(lo,hi,s) asm("mov.b64 {%0, %1}, %2;" : "=r"(lo), "=r"(hi) : "l"(s))

// ---------------------------------------------------------------------------
// Scratch (static device memory; no allocation allowed)
// ---------------------------------------------------------------------------
__device__ float g_y[TOT];       // conv2d output
__device__ float g_m[TOT];       // mamba output (pre-GroupNorm)
__device__ float g_stats[16];    // (b,group) -> {sum, sumsq}

// ---------------------------------------------------------------------------
// Kernel 1: 3x3 conv, 128->128 ch, pad 1, + bias. FFMA2 (f32x2) path.
// Grid: (4, 128, 2): bx -> {cog(64 co), wseg(64 w)}, by=h, bz=b. Block 256.
// Thread: 2 co x 8 w outputs. Also block(0,0,0) zeroes GroupNorm stats.
// ---------------------------------------------------------------------------
__global__ __launch_bounds__(256) void conv3x3_kernel(
    const float* __restrict__ x, const float* __restrict__ w,
    const float* __restrict__ bias)
{
    __shared__ __align__(16) float xs[16][3][72];   // 66 cols used (64 + halo)
    __shared__ float ws[64 * 146];                  // stride 146: bank-spread

    const int bx  = blockIdx.x;
    const int cog = bx >> 1;          // 0..1 (64 co each)
    const int w0  = (bx & 1) << 6;    // 0 or 64
    const int h   = blockIdx.y;
    const int b   = blockIdx.z;
    const int tid = threadIdx.x;
    const int cp  = tid >> 3;         // 0..31 co-pair
    const int wl  = (tid & 7) << 3;   // 0..56 local w base

    if (bx == 0 && h == 0 && b == 0 && tid < 16) g_stats[tid] = 0.f;

    u64 accA[4], accB[4];
#pragma unroll
    for (int j = 0; j < 4; j++) { accA[j] = 0ull; accB[j] = 0ull; }

    const float* wsrcBase = w + (size_t)(cog * 64) * 1152;

    for (int ci0 = 0; ci0 < CH; ci0 += 16) {
        // load input patch: 16 ci x 3 rows x 66 cols (zero-padded at edges)
        for (int idx = tid; idx < 16 * 3 * 66; idx += 256) {
            int ci  = idx / 198;
            int rem = idx - ci * 198;
            int r   = rem / 66;
            int col = rem - r * 66;
            int hh  = h - 1 + r;
            int wg  = w0 - 1 + col;
            float v = 0.f;
            if ((unsigned)hh < HH && (unsigned)wg < WW)
                v = x[(((b * CH + ci0 + ci) * HH + hh) << 7) + wg];
            xs[ci][r][col] = v;
        }
        // load weights: 64 co x 144 (16 ci x 9)
        const float* wsrc = wsrcBase + ci0 * 9;
        for (int idx = tid; idx < 64 * 144; idx += 256) {
            int coi = idx / 144;
            int rem = idx - coi * 144;
            ws[coi * 146 + rem] = wsrc[coi * 1152 + rem];
        }
        __syncthreads();

#pragma unroll 2
        for (int ci = 0; ci < 16; ci++) {
            float wA[9], wB[9];
            const float* wpA = &ws[(cp * 2) * 146 + ci * 9];
#pragma unroll
            for (int k = 0; k < 9; k++) { wA[k] = wpA[k]; wB[k] = wpA[146 + k]; }
#pragma unroll
            for (int r = 0; r < 3; r++) {
                const float* xp = &xs[ci][r][wl];
                float4 q0 = *(const float4*)xp;
                float4 q1 = *(const float4*)(xp + 4);
                float2 q2 = *(const float2*)(xp + 8);
                float rr[10];
                rr[0]=q0.x; rr[1]=q0.y; rr[2]=q0.z; rr[3]=q0.w;
                rr[4]=q1.x; rr[5]=q1.y; rr[6]=q1.z; rr[7]=q1.w;
                rr[8]=q2.x; rr[9]=q2.y;
                u64 p[9];
#pragma unroll
                for (int s = 0; s < 9; s++) PK2(p[s], rr[s], rr[s + 1]);
#pragma unroll
                for (int kw = 0; kw < 3; kw++) {
                    float fa = wA[r * 3 + kw], fb = wB[r * 3 + kw];
                    u64 wa2, wb2;
                    PK2(wa2, fa, fa);
                    PK2(wb2, fb, fb);
#pragma unroll
                    for (int j = 0; j < 4; j++) {
                        FMA2(accA[j], wa2, p[2 * j + kw], accA[j]);
                        FMA2(accB[j], wb2, p[2 * j + kw], accB[j]);
                    }
                }
            }
        }
        __syncthreads();
    }

    const int coA = cog * 64 + cp * 2;
    const float bA = bias[coA], bB = bias[coA + 1];
    float oA[8], oB[8];
#pragma unroll
    for (int j = 0; j < 4; j++) {
        unsigned lo, hi;
        UPK2(lo, hi, accA[j]);
        oA[2 * j] = __uint_as_float(lo) + bA; oA[2 * j + 1] = __uint_as_float(hi) + bA;
        UPK2(lo, hi, accB[j]);
        oB[2 * j] = __uint_as_float(lo) + bB; oB[2 * j + 1] = __uint_as_float(hi) + bB;
    }
    float* ypA = &g_y[(((b * CH + coA) * HH + h) << 7) + w0 + wl];
    float* ypB = ypA + HH * WW;
    *(float4*)ypA       = make_float4(oA[0], oA[1], oA[2], oA[3]);
    *(float4*)(ypA + 4) = make_float4(oA[4], oA[5], oA[6], oA[7]);
    *(float4*)ypB       = make_float4(oB[0], oB[1], oB[2], oB[3]);
    *(float4*)(ypB + 4) = make_float4(oB[4], oB[5], oB[6], oB[7]);
}

// ---------------------------------------------------------------------------
// Kernel 2: Mamba over 32768 sequences, one warp per sequence (lane = d_inner).
// Also accumulates GroupNorm sum/sumsq (group is constant per block).
// Grid: 4096 blocks x 256 threads (8 warps).
// ---------------------------------------------------------------------------
__global__ __launch_bounds__(256) void mamba_kernel(
    const float* __restrict__ in_proj_w,   // (64,16)
    const float* __restrict__ c1w,         // (32,1,4)
    const float* __restrict__ c1b,         // (32)
    const float* __restrict__ xpw,         // (33,32)
    const float* __restrict__ dtw,         // (32,1)
    const float* __restrict__ dtb,         // (32)
    const float* __restrict__ A_log,       // (32,16)
    const float* __restrict__ Dp,          // (32)
    const float* __restrict__ opw)         // (16,32)
{
    __shared__ float s_ipw[16 * 64];    // [k][e]
    __shared__ float s_xpwt[32 * 33];   // [d][e]
    __shared__ float s_At[16 * 32];     // [s][d] : A = -exp(A_log)
    __shared__ float s_opwt[32 * 16];   // [d][g]
    __shared__ float s_c1w[32 * 4];
    __shared__ float s_c1b[32], s_dtw[32], s_dtb[32], s_D[32];
    __shared__ float s_seq[8][128];
    __shared__ float s_xc[8][LSEQ * 32];
    __shared__ float s_bc[8][LSEQ * 32];
    __shared__ float sm_s1, sm_s2;

    const int tid = threadIdx.x;

    for (int idx = tid; idx < 16 * 64; idx += 256) {
        int k = idx >> 6, e = idx & 63;
        s_ipw[idx] = in_proj_w[e * 16 + k];
    }
    for (int idx = tid; idx < 32 * 33; idx += 256) {
        int d = idx / 33, e = idx - d * 33;
        s_xpwt[idx] = xpw[e * 32 + d];
    }
    for (int idx = tid; idx < 16 * 32; idx += 256) {
        int s = idx >> 5, d = idx & 31;
        s_At[idx] = -__expf(A_log[d * 16 + s]);
    }
    for (int idx = tid; idx < 32 * 16; idx += 256) {
        int d = idx >> 4, g = idx & 15;
        s_opwt[idx] = opw[g * 32 + d];
    }
    if (tid < 128) s_c1w[tid] = c1w[tid];
    if (tid < 32) {
        s_c1b[tid] = c1b[tid];
        s_dtw[tid] = dtw[tid];
        s_dtb[tid] = dtb[tid];
        s_D[tid]   = Dp[tid];
    }
    if (tid == 0) { sm_s1 = 0.f; sm_s2 = 0.f; }
    __syncthreads();

    const int warp = tid >> 5;
    const int lane = tid & 31;
    const int n = blockIdx.x * 8 + warp;
    const int c = (n >> 7) & 127;
    const int b = n >> 14;

    const float* yrow = g_y + (size_t)n * 128;
    float* seq = s_seq[warp];
#pragma unroll
    for (int i = 0; i < 4; i++) seq[i * 32 + lane] = yrow[i * 32 + lane];
    __syncwarp();

    float xi[LSEQ], zv[LSEQ];
#pragma unroll
    for (int l = 0; l < LSEQ; l++) {
        float sx = 0.f, sz = 0.f;
#pragma unroll
        for (int k = 0; k < GCN; k++) {
            float sv = seq[l * GCN + k];
            sx = fmaf(sv, s_ipw[k * 64 + lane], sx);
            sz = fmaf(sv, s_ipw[k * 64 + 32 + lane], sz);
        }
        xi[l] = sx; zv[l] = sz;
    }

    float cw0 = s_c1w[lane * 4 + 0], cw1 = s_c1w[lane * 4 + 1];
    float cw2 = s_c1w[lane * 4 + 2], cw3 = s_c1w[lane * 4 + 3];
    float cb = s_c1b[lane];
    float xc[LSEQ];
#pragma unroll
    for (int l = 0; l < LSEQ; l++) {
        float a = fmaf(cw3, xi[l], cb);
        if (l >= 1) a = fmaf(cw2, xi[l - 1], a);
        if (l >= 2) a = fmaf(cw1, xi[l - 2], a);
        if (l >= 3) a = fmaf(cw0, xi[l - 3], a);
        a = a * (1.f / (1.f + __expf(-a)));
        xc[l] = a;
        s_xc[warp][l * 32 + lane] = a;
    }
    __syncwarp();

    float dtin[LSEQ];
#pragma unroll
    for (int l = 0; l < LSEQ; l++) {
        float s0 = 0.f, s1 = 0.f;
#pragma unroll
        for (int d = 0; d < D_INNER; d++) {
            float xv = s_xc[warp][l * 32 + d];
            s0 = fmaf(xv, s_xpwt[d * 33], s0);
            s1 = fmaf(xv, s_xpwt[d * 33 + 1 + lane], s1);
        }
        dtin[l] = s0;
        s_bc[warp][l * 32 + lane] = s1;
    }
    __syncwarp();

    float Areg[D_STATE];
#pragma unroll
    for (int s = 0; s < D_STATE; s++) Areg[s] = s_At[s * 32 + lane];
    float hreg[D_STATE];
#pragma unroll
    for (int s = 0; s < D_STATE; s++) hreg[s] = 0.f;

    const float dtwv = s_dtw[lane], dtbv = s_dtb[lane], Dv = s_D[lane];

#pragma unroll
    for (int l = 0; l < LSEQ; l++) {
        float pre = fmaf(dtin[l], dtwv, dtbv);
        float dt = (pre > 20.f) ? pre : log1pf(__expf(pre));
        float cBx = dt * xc[l];
        float yacc = 0.f;
#pragma unroll
        for (int s = 0; s < D_STATE; s++) {
            float dA = __expf(dt * Areg[s]);
            float Bv = s_bc[warp][l * 32 + s];
            float Cv = s_bc[warp][l * 32 + 16 + s];
            hreg[s] = fmaf(dA, hreg[s], cBx * Bv);
            yacc = fmaf(hreg[s], Cv, yacc);
        }
        float ym = fmaf(Dv, xc[l], yacc);
        float zz = zv[l];
        ym = ym * (zz * (1.f / (1.f + __expf(-zz))));
        s_xc[warp][l * 32 + lane] = ym;
    }
    __syncwarp();

    float ps1 = 0.f, ps2 = 0.f;
    const int g = lane & 15;
    const int lh = lane >> 4;
    float* outp = g_m + (size_t)n * 128;
#pragma unroll
    for (int i = 0; i < 4; i++) {
        int l = i * 2 + lh;
        float acc = 0.f;
#pragma unroll
        for (int d = 0; d < D_INNER; d++)
            acc = fmaf(s_xc[warp][l * 32 + d], s_opwt[d * 16 + g], acc);
        outp[l * GCN + g] = acc;
        ps1 += acc;
        ps2 = fmaf(acc, acc, ps2);
    }

#pragma unroll
    for (int off = 16; off; off >>= 1) {
        ps1 += __shfl_xor_sync(0xFFFFFFFFu, ps1, off);
        ps2 += __shfl_xor_sync(0xFFFFFFFFu, ps2, off);
    }
    if (lane == 0) {
        atomicAdd(&sm_s1, ps1);
        atomicAdd(&sm_s2, ps2);
    }
    __syncthreads();
    if (tid == 0) {
        int bg = b * 4 + (c >> 5);
        atomicAdd(&g_stats[bg * 2 + 0], sm_s1);
        atomicAdd(&g_stats[bg * 2 + 1], sm_s2);
    }
}

// ---------------------------------------------------------------------------
// Kernel 3: GroupNorm + SiLU + residual add. float4.
// ---------------------------------------------------------------------------
__global__ __launch_bounds__(256) void apply_kernel(
    const float* __restrict__ x, const float* __restrict__ gnw,
    const float* __restrict__ gnb, float* __restrict__ out)
{
    int idx4 = blockIdx.x * blockDim.x + threadIdx.x;
    if (idx4 >= TOT / 4) return;
    int idx = idx4 * 4;
    int c  = (idx >> 14) & 127;
    int bg = (idx >> 21) * 4 + (c >> 5);
    float s1 = g_stats[bg * 2], s2 = g_stats[bg * 2 + 1];
    const float inv_cnt = 1.f / (float)GRP_CNT;
    float mu  = s1 * inv_cnt;
    float var = fmaf(s2, inv_cnt, -mu * mu);
    float rstd = rsqrtf(var + 1e-5f);
    float gw = gnw[c] * rstd;
    float gb = gnb[c];

    float4 xv = *(const float4*)&x[idx];
    float4 mv = *(const float4*)&g_m[idx];
    float4 o;
    { float t = fmaf(mv.x - mu, gw, gb); o.x = xv.x + t * (1.f / (1.f + __expf(-t))); }
    { float t = fmaf(mv.y - mu, gw, gb); o.y = xv.y + t * (1.f / (1.f + __expf(-t))); }
    { float t = fmaf(mv.z - mu, gw, gb); o.z = xv.z + t * (1.f / (1.f + __expf(-t))); }
    { float t = fmaf(mv.w - mu, gw, gb); o.w = xv.w + t * (1.f / (1.f + __expf(-t))); }
    *(float4*)&out[idx] = o;
}

// ---------------------------------------------------------------------------
// Launch
// ---------------------------------------------------------------------------
extern "C" void kernel_launch(void* const* d_in, const int* in_sizes, int n_in,
                              void* d_out, int out_size)
{
    const float* x          = (const float*)d_in[0];
    const float* conv_w     = (const float*)d_in[1];
    const float* conv_b     = (const float*)d_in[2];
    const float* gn_w       = (const float*)d_in[3];
    const float* gn_b       = (const float*)d_in[4];
    const float* in_proj_w  = (const float*)d_in[5];
    const float* conv1d_w   = (const float*)d_in[6];
    const float* conv1d_b   = (const float*)d_in[7];
    const float* x_proj_w   = (const float*)d_in[8];
    const float* dt_proj_w  = (const float*)d_in[9];
    const float* dt_proj_b  = (const float*)d_in[10];
    const float* A_log      = (const float*)d_in[11];
    const float* Dp         = (const float*)d_in[12];
    const float* out_proj_w = (const float*)d_in[13];
    float* out = (float*)d_out;

    dim3 cgrid(4, HH, BN);
    conv3x3_kernel<<<cgrid, 256>>>(x, conv_w, conv_b);

    mamba_kernel<<<NSEQ / 8, 256>>>(in_proj_w, conv1d_w, conv1d_b, x_proj_w,
                                    dt_proj_w, dt_proj_b, A_log, Dp, out_proj_w);

    apply_kernel<<<(TOT / 4 + 255) / 256, 256>>>(x, gn_w, gn_b, out);
}

// round 7
// speedup vs baseline: 5.7180x; 1.6169x over previous
#include <cuda_runtime.h>
#include <cuda_bf16.h>
#include <math.h>
#include <stdint.h>

// ---------------------------------------------------------------------------
// Problem constants
// ---------------------------------------------------------------------------
#define BN   2
#define CH   128
#define HH   128
#define WW   128
#define TOT  (BN*CH*HH*WW)          // 4194304
#define NSEQ (BN*CH*HH)             // 32768 sequences
#define D_INNER 32
#define D_STATE 16
#define GCN  16
#define LSEQ 8
#define GROUPS 4
#define GRP_CNT ((CH/GROUPS)*HH*WW) // 524288 per (b, group)

// ---------------------------------------------------------------------------
// Scratch (static device memory; no allocation allowed)
// ---------------------------------------------------------------------------
__device__ float g_y[TOT];       // conv2d output
__device__ float g_m[TOT];       // mamba output (pre-GroupNorm)
__device__ float g_stats[16];    // (b,group) -> {sum, sumsq}
// weight tiles: [tap 0..8][half 0..1], each 128ci x 128co bf16, swizzled, 32KB
__device__ __align__(16) unsigned char g_wt[18 * 32768];

// smem layout for conv kernel (dynamic):
//  [0,       34816)  A hi tile: 136 rows(wp) x 128 ci bf16, 256B rows, swizzled
//  [34816,   69632)  A lo tile
//  [69632,  168000)  3 weight buffers x 32768
//  bounce (epilogue) reuses [0, 67584): 128 w x 132 co f32
#define AH_OFF 0
#define AL_OFF 34816
#define W_OFF  69632
#define CSMEM  (W_OFF + 3*32768)   // 167936

// swizzle: off = row*256 + col2B; phys = off ^ ((row&7)<<4)
__host__ __device__ __forceinline__ uint32_t swz(uint32_t row, uint32_t colByte) {
    uint32_t off = row * 256u + colByte;
    return off ^ ((row & 7u) << 4);
}

__device__ __forceinline__ uint32_t smem_u32(const void* p) {
    uint32_t a;
    asm("{ .reg .u64 t; cvta.to.shared.u64 t, %1; cvt.u32.u64 %0, t; }" : "=r"(a) : "l"(p));
    return a;
}

#define LDSM_X4(r0,r1,r2,r3,addr) \
    asm volatile("ldmatrix.sync.aligned.m8n8.x4.shared.b16 {%0,%1,%2,%3}, [%4];" \
        : "=r"(r0), "=r"(r1), "=r"(r2), "=r"(r3) : "r"(addr))
#define LDSM_X4_T(r0,r1,r2,r3,addr) \
    asm volatile("ldmatrix.sync.aligned.m8n8.x4.trans.shared.b16 {%0,%1,%2,%3}, [%4];" \
        : "=r"(r0), "=r"(r1), "=r"(r2), "=r"(r3) : "r"(addr))
#define MMA16816(c0,c1,c2,c3,a0,a1,a2,a3,b0,b1) \
    asm volatile("mma.sync.aligned.m16n8k16.row.col.f32.bf16.bf16.f32 " \
        "{%0,%1,%2,%3}, {%4,%5,%6,%7}, {%8,%9}, {%0,%1,%2,%3};" \
        : "+f"(c0), "+f"(c1), "+f"(c2), "+f"(c3) \
        : "r"(a0), "r"(a1), "r"(a2), "r"(a3), "r"(b0), "r"(b1))
#define CP_ASYNC16(dst, src) \
    asm volatile("cp.async.cg.shared.global [%0], [%1], 16;" :: "r"(dst), "l"(src))
#define CP_COMMIT() asm volatile("cp.async.commit_group;")

// ---------------------------------------------------------------------------
// Prep: conv weights -> bf16 hi/lo swizzled [ci][co] tiles; zero stats
// ---------------------------------------------------------------------------
__global__ void prep_kernel(const float* __restrict__ cw) {
    int idx = blockIdx.x * 256 + threadIdx.x;
    if (blockIdx.x == 0 && threadIdx.x < 16) g_stats[threadIdx.x] = 0.f;
    if (idx >= 9 * 128 * 128) return;
    int tap = idx >> 14;
    int rem = idx & 16383;
    int ci = rem >> 7, co = rem & 127;
    float v = cw[co * 1152 + ci * 9 + tap];
    __nv_bfloat16 hv = __float2bfloat16(v);
    __nv_bfloat16 lv = __float2bfloat16(v - __bfloat162float(hv));
    uint32_t o = swz((uint32_t)ci, (uint32_t)co * 2u);
    *(__nv_bfloat16*)(g_wt + (size_t)(tap * 2 + 0) * 32768 + o) = hv;
    *(__nv_bfloat16*)(g_wt + (size_t)(tap * 2 + 1) * 32768 + o) = lv;
}

// ---------------------------------------------------------------------------
// Conv 3x3 via mma.sync (bf16 split hi/lo, 3 passes). One block = one (b,h).
// D[w][co] single accumulator; tap w-shift = A row offset at ldmatrix.
// ---------------------------------------------------------------------------
__global__ __launch_bounds__(256, 1) void conv_mma_kernel(
    const float* __restrict__ x, const float* __restrict__ bias)
{
    extern __shared__ __align__(1024) char smem[];
    const uint32_t sb = smem_u32(smem);
    const int tid = threadIdx.x, warp = tid >> 5, lane = tid & 31;
    const int h = blockIdx.x, b = blockIdx.y;
    const int m0 = warp * 16;           // w-row base for this warp

    float acc[64];
#pragma unroll
    for (int i = 0; i < 64; i++) acc[i] = 0.f;

    // prologue: prefetch weight tiles 0,1
    {
        const char* src = (const char*)g_wt + tid * 16;
        uint32_t dst = sb + W_OFF + tid * 16;
#pragma unroll
        for (int i = 0; i < 8; i++) CP_ASYNC16(dst + i * 4096, src + i * 4096);
        CP_COMMIT();
        src += 32768; dst += 32768;
#pragma unroll
        for (int i = 0; i < 8; i++) CP_ASYNC16(dst + i * 4096, src + i * 4096);
        CP_COMMIT();
    }
    int issued = 2, ready = -1;

#pragma unroll 1
    for (int dh = 0; dh < 3; dh++) {
        __syncthreads();   // everyone done reading previous A
        // ---- build A tiles (hi/lo) for input row hr ----
        {
            const int hr = h + dh - 1;
            const bool valid = (hr >= 0) && (hr < HH);
            // zero halo rows 0 and 129
            {
                uint32_t rz = (tid & 128) ? 129u : 0u;
                uint32_t ciz = (uint32_t)(tid & 127);
                uint32_t o = swz(rz, ciz * 2u);
                *(__nv_bfloat16*)(smem + AH_OFF + o) = __float2bfloat16(0.f);
                *(__nv_bfloat16*)(smem + AL_OFF + o) = __float2bfloat16(0.f);
            }
#pragma unroll 1
            for (int k = 0; k < 16; k++) {
                const int ci = warp + 8 * k;
                float4 q = make_float4(0.f, 0.f, 0.f, 0.f);
                if (valid)
                    q = *(const float4*)&x[((b * CH + ci) * HH + hr) * WW + lane * 4];
                float vv[4] = {q.x, q.y, q.z, q.w};
#pragma unroll
                for (int e = 0; e < 4; e++) {
                    uint32_t wp = (uint32_t)(lane * 4 + e + 1);
                    __nv_bfloat16 hv = __float2bfloat16(vv[e]);
                    __nv_bfloat16 lv = __float2bfloat16(vv[e] - __bfloat162float(hv));
                    uint32_t o = swz(wp, (uint32_t)ci * 2u);
                    *(__nv_bfloat16*)(smem + AH_OFF + o) = hv;
                    *(__nv_bfloat16*)(smem + AL_OFF + o) = lv;
                }
            }
        }
        __syncthreads();

#pragma unroll 1
        for (int dw = 0; dw < 3; dw++) {
#pragma unroll 1
            for (int pp = 0; pp < 3; pp++) {
                // pp0: Wh*Ah, pp1: Wh*Al, pp2: Wl*Ah
                const int whalf = (pp == 2);
                const int ahalf = (pp == 1);
                const int L = (dh * 3 + dw) * 2 + whalf;
                if (L > ready) {
                    if (L == 17) { asm volatile("cp.async.wait_group 0;"); }
                    else         { asm volatile("cp.async.wait_group 1;"); }
                    ready = L;
                    __syncthreads();
                    if (issued < 18) {
                        const char* src = (const char*)g_wt + (size_t)issued * 32768 + tid * 16;
                        uint32_t dst = sb + W_OFF + (uint32_t)(issued % 3) * 32768 + tid * 16;
#pragma unroll
                        for (int i = 0; i < 8; i++) CP_ASYNC16(dst + i * 4096, src + i * 4096);
                        CP_COMMIT();
                        issued++;
                    }
                }
                const uint32_t aB = sb + (ahalf ? AL_OFF : AH_OFF);
                const uint32_t wB = sb + W_OFF + (uint32_t)(L % 3) * 32768;
                // A ldmatrix lane geometry
                const uint32_t arow = (uint32_t)(m0 + dw + ((lane >> 3) & 1) * 8 + (lane & 7));
                const uint32_t arbase = aB + arow * 256u;
                const uint32_t axor = (arow & 7u) << 4;
                const uint32_t brow = (uint32_t)(lane & 15);
                const uint32_t bg = (uint32_t)(lane >> 4);
#pragma unroll
                for (int ks = 0; ks < 8; ks++) {
                    uint32_t a0, a1, a2, a3;
                    uint32_t aaddr = arbase + ((((uint32_t)(ks * 2) + bg) << 4) ^ axor);
                    LDSM_X4(a0, a1, a2, a3, aaddr);
                    const uint32_t br = (uint32_t)(ks * 16) + brow;
                    const uint32_t brbase = wB + br * 256u;
                    const uint32_t bxor = (br & 7u) << 4;
#pragma unroll
                    for (int j2 = 0; j2 < 8; j2++) {
                        uint32_t b0, b1, b2, b3;
                        uint32_t baddr = brbase + ((((uint32_t)(j2 * 2) + bg) << 4) ^ bxor);
                        LDSM_X4_T(b0, b1, b2, b3, baddr);
                        MMA16816(acc[j2 * 8 + 0], acc[j2 * 8 + 1], acc[j2 * 8 + 2], acc[j2 * 8 + 3],
                                 a0, a1, a2, a3, b0, b1);
                        MMA16816(acc[j2 * 8 + 4], acc[j2 * 8 + 5], acc[j2 * 8 + 6], acc[j2 * 8 + 7],
                                 a0, a1, a2, a3, b2, b3);
                    }
                }
            }
        }
    }

    // ---- epilogue: regs -> bounce[w][co] (+bias) -> transposed global ----
    __syncthreads();
    {
        float* bounce = (float*)smem;          // [128][132]
        const int q = lane >> 2, p = lane & 3;
        const int r0 = m0 + q, r1 = m0 + q + 8;
#pragma unroll
        for (int j = 0; j < 16; j++) {
            const int co = j * 8 + p * 2;
            float2 bv = *(const float2*)&bias[co];
            *(float2*)&bounce[r0 * 132 + co] =
                make_float2(acc[j * 4 + 0] + bv.x, acc[j * 4 + 1] + bv.y);
            *(float2*)&bounce[r1 * 132 + co] =
                make_float2(acc[j * 4 + 2] + bv.x, acc[j * 4 + 3] + bv.y);
        }
        __syncthreads();
        const int co2 = tid >> 1, seg = (tid & 1) * 64;
        float* dst = &g_y[((b * CH + co2) * HH + h) * WW + seg];
#pragma unroll
        for (int j = 0; j < 64; j += 4) {
            *(float4*)&dst[j] = make_float4(
                bounce[(seg + j + 0) * 132 + co2], bounce[(seg + j + 1) * 132 + co2],
                bounce[(seg + j + 2) * 132 + co2], bounce[(seg + j + 3) * 132 + co2]);
        }
    }
}

// ---------------------------------------------------------------------------
// Mamba kernel (validated): one warp per sequence, lane = d_inner channel.
// ---------------------------------------------------------------------------
__global__ __launch_bounds__(256) void mamba_kernel(
    const float* __restrict__ in_proj_w, const float* __restrict__ c1w,
    const float* __restrict__ c1b, const float* __restrict__ xpw,
    const float* __restrict__ dtw, const float* __restrict__ dtb,
    const float* __restrict__ A_log, const float* __restrict__ Dp,
    const float* __restrict__ opw)
{
    __shared__ float s_ipw[16 * 64];
    __shared__ float s_xpwt[32 * 33];
    __shared__ float s_At[16 * 32];
    __shared__ float s_opwt[32 * 16];
    __shared__ float s_c1w[32 * 4];
    __shared__ float s_c1b[32], s_dtw[32], s_dtb[32], s_D[32];
    __shared__ float s_seq[8][128];
    __shared__ float s_xc[8][LSEQ * 32];
    __shared__ float s_bc[8][LSEQ * 32];
    __shared__ float sm_s1, sm_s2;

    const int tid = threadIdx.x;

    for (int idx = tid; idx < 16 * 64; idx += 256) {
        int k = idx >> 6, e = idx & 63;
        s_ipw[idx] = in_proj_w[e * 16 + k];
    }
    for (int idx = tid; idx < 32 * 33; idx += 256) {
        int d = idx / 33, e = idx - d * 33;
        s_xpwt[idx] = xpw[e * 32 + d];
    }
    for (int idx = tid; idx < 16 * 32; idx += 256) {
        int s = idx >> 5, d = idx & 31;
        s_At[idx] = -__expf(A_log[d * 16 + s]);
    }
    for (int idx = tid; idx < 32 * 16; idx += 256) {
        int d = idx >> 4, g = idx & 15;
        s_opwt[idx] = opw[g * 32 + d];
    }
    if (tid < 128) s_c1w[tid] = c1w[tid];
    if (tid < 32) {
        s_c1b[tid] = c1b[tid];
        s_dtw[tid] = dtw[tid];
        s_dtb[tid] = dtb[tid];
        s_D[tid]   = Dp[tid];
    }
    if (tid == 0) { sm_s1 = 0.f; sm_s2 = 0.f; }
    __syncthreads();

    const int warp = tid >> 5;
    const int lane = tid & 31;
    const int n = blockIdx.x * 8 + warp;
    const int c = (n >> 7) & 127;
    const int b = n >> 14;

    const float* yrow = g_y + (size_t)n * 128;
    float* seq = s_seq[warp];
#pragma unroll
    for (int i = 0; i < 4; i++) seq[i * 32 + lane] = yrow[i * 32 + lane];
    __syncwarp();

    float xi[LSEQ], zv[LSEQ];
#pragma unroll
    for (int l = 0; l < LSEQ; l++) {
        float sx = 0.f, sz = 0.f;
#pragma unroll
        for (int k = 0; k < GCN; k++) {
            float sv = seq[l * GCN + k];
            sx = fmaf(sv, s_ipw[k * 64 + lane], sx);
            sz = fmaf(sv, s_ipw[k * 64 + 32 + lane], sz);
        }
        xi[l] = sx; zv[l] = sz;
    }

    float cw0 = s_c1w[lane * 4 + 0], cw1 = s_c1w[lane * 4 + 1];
    float cw2 = s_c1w[lane * 4 + 2], cw3 = s_c1w[lane * 4 + 3];
    float cb = s_c1b[lane];
    float xc[LSEQ];
#pragma unroll
    for (int l = 0; l < LSEQ; l++) {
        float a = fmaf(cw3, xi[l], cb);
        if (l >= 1) a = fmaf(cw2, xi[l - 1], a);
        if (l >= 2) a = fmaf(cw1, xi[l - 2], a);
        if (l >= 3) a = fmaf(cw0, xi[l - 3], a);
        a = a * (1.f / (1.f + __expf(-a)));
        xc[l] = a;
        s_xc[warp][l * 32 + lane] = a;
    }
    __syncwarp();

    float dtin[LSEQ];
#pragma unroll
    for (int l = 0; l < LSEQ; l++) {
        float s0 = 0.f, s1 = 0.f;
#pragma unroll
        for (int d = 0; d < D_INNER; d++) {
            float xv = s_xc[warp][l * 32 + d];
            s0 = fmaf(xv, s_xpwt[d * 33], s0);
            s1 = fmaf(xv, s_xpwt[d * 33 + 1 + lane], s1);
        }
        dtin[l] = s0;
        s_bc[warp][l * 32 + lane] = s1;
    }
    __syncwarp();

    float Areg[D_STATE];
#pragma unroll
    for (int s = 0; s < D_STATE; s++) Areg[s] = s_At[s * 32 + lane];
    float hreg[D_STATE];
#pragma unroll
    for (int s = 0; s < D_STATE; s++) hreg[s] = 0.f;

    const float dtwv = s_dtw[lane], dtbv = s_dtb[lane], Dv = s_D[lane];

#pragma unroll
    for (int l = 0; l < LSEQ; l++) {
        float pre = fmaf(dtin[l], dtwv, dtbv);
        float dt = (pre > 20.f) ? pre : log1pf(__expf(pre));
        float cBx = dt * xc[l];
        float yacc = 0.f;
#pragma unroll
        for (int s = 0; s < D_STATE; s++) {
            float dA = __expf(dt * Areg[s]);
            float Bv = s_bc[warp][l * 32 + s];
            float Cv = s_bc[warp][l * 32 + 16 + s];
            hreg[s] = fmaf(dA, hreg[s], cBx * Bv);
            yacc = fmaf(hreg[s], Cv, yacc);
        }
        float ym = fmaf(Dv, xc[l], yacc);
        float zz = zv[l];
        ym = ym * (zz * (1.f / (1.f + __expf(-zz))));
        s_xc[warp][l * 32 + lane] = ym;
    }
    __syncwarp();

    float ps1 = 0.f, ps2 = 0.f;
    const int g = lane & 15;
    const int lh = lane >> 4;
    float* outp = g_m + (size_t)n * 128;
#pragma unroll
    for (int i = 0; i < 4; i++) {
        int l = i * 2 + lh;
        float a2 = 0.f;
#pragma unroll
        for (int d = 0; d < D_INNER; d++)
            a2 = fmaf(s_xc[warp][l * 32 + d], s_opwt[d * 16 + g], a2);
        outp[l * GCN + g] = a2;
        ps1 += a2;
        ps2 = fmaf(a2, a2, ps2);
    }

#pragma unroll
    for (int off = 16; off; off >>= 1) {
        ps1 += __shfl_xor_sync(0xFFFFFFFFu, ps1, off);
        ps2 += __shfl_xor_sync(0xFFFFFFFFu, ps2, off);
    }
    if (lane == 0) {
        atomicAdd(&sm_s1, ps1);
        atomicAdd(&sm_s2, ps2);
    }
    __syncthreads();
    if (tid == 0) {
        int bg = b * 4 + (c >> 5);
        atomicAdd(&g_stats[bg * 2 + 0], sm_s1);
        atomicAdd(&g_stats[bg * 2 + 1], sm_s2);
    }
}

// ---------------------------------------------------------------------------
// GroupNorm + SiLU + residual
// ---------------------------------------------------------------------------
__global__ __launch_bounds__(256) void apply_kernel(
    const float* __restrict__ x, const float* __restrict__ gnw,
    const float* __restrict__ gnb, float* __restrict__ out)
{
    int idx4 = blockIdx.x * blockDim.x + threadIdx.x;
    if (idx4 >= TOT / 4) return;
    int idx = idx4 * 4;
    int c  = (idx >> 14) & 127;
    int bg = (idx >> 21) * 4 + (c >> 5);
    float s1 = g_stats[bg * 2], s2 = g_stats[bg * 2 + 1];
    const float inv_cnt = 1.f / (float)GRP_CNT;
    float mu  = s1 * inv_cnt;
    float var = fmaf(s2, inv_cnt, -mu * mu);
    float rstd = rsqrtf(var + 1e-5f);
    float gw = gnw[c] * rstd;
    float gb = gnb[c];

    float4 xv = *(const float4*)&x[idx];
    float4 mv = *(const float4*)&g_m[idx];
    float4 o;
    { float t = fmaf(mv.x - mu, gw, gb); o.x = xv.x + t * (1.f / (1.f + __expf(-t))); }
    { float t = fmaf(mv.y - mu, gw, gb); o.y = xv.y + t * (1.f / (1.f + __expf(-t))); }
    { float t = fmaf(mv.z - mu, gw, gb); o.z = xv.z + t * (1.f / (1.f + __expf(-t))); }
    { float t = fmaf(mv.w - mu, gw, gb); o.w = xv.w + t * (1.f / (1.f + __expf(-t))); }
    *(float4*)&out[idx] = o;
}

// ---------------------------------------------------------------------------
// Launch
// ---------------------------------------------------------------------------
extern "C" void kernel_launch(void* const* d_in, const int* in_sizes, int n_in,
                              void* d_out, int out_size)
{
    const float* x          = (const float*)d_in[0];
    const float* conv_w     = (const float*)d_in[1];
    const float* conv_b     = (const float*)d_in[2];
    const float* gn_w       = (const float*)d_in[3];
    const float* gn_b       = (const float*)d_in[4];
    const float* in_proj_w  = (const float*)d_in[5];
    const float* conv1d_w   = (const float*)d_in[6];
    const float* conv1d_b   = (const float*)d_in[7];
    const float* x_proj_w   = (const float*)d_in[8];
    const float* dt_proj_w  = (const float*)d_in[9];
    const float* dt_proj_b  = (const float*)d_in[10];
    const float* A_log      = (const float*)d_in[11];
    const float* Dp         = (const float*)d_in[12];
    const float* out_proj_w = (const float*)d_in[13];
    float* out = (float*)d_out;

    static int smem_set = 0;
    if (!smem_set) {
        cudaFuncSetAttribute(conv_mma_kernel,
                             cudaFuncAttributeMaxDynamicSharedMemorySize, CSMEM);
        smem_set = 1;
    }

    prep_kernel<<<576, 256>>>(conv_w);

    dim3 cgrid(HH, BN);
    conv_mma_kernel<<<cgrid, 256, CSMEM>>>(x, conv_b);

    mamba_kernel<<<NSEQ / 8, 256>>>(in_proj_w, conv1d_w, conv1d_b, x_proj_w,
                                    dt_proj_w, dt_proj_b, A_log, Dp, out_proj_w);

    apply_kernel<<<(TOT / 4 + 255) / 256, 256>>>(x, gn_w, gn_b, out);
}